// round 17
// baseline (speedup 1.0000x reference)
#include <cuda_runtime.h>
#include <cuda_bf16.h>
#include <cstdint>

// TemporalGCN — 2 (b,t) per block, 128 threads. ALL phases on tensor cores.
//  A': yT[h,c]  = W0 @ x^T      (M=128,N=48,K=192)  W-frags prepacked in gmem
//  M1: y2[c,h]  = relu(b0 + A48 @ y)   (M=48,N=128,K=48)  A48 = blockdiag bf16
//  C': y3T[h,c] = W1 @ y2^T     (M=128,N=48,K=128)
//  M2: out      = mean_c relu(b1 + A48 @ y3)  (shfl-reduced epilogue)
// All GEMMs bf16x3 split (hi*hi + lo*hi + hi*lo).

#define NBLK 8192
#define NW0  (12*8*4*32)   // 12288 A-frag-packed W0 (ks,mi,r,lane)
#define NW1  (8*8*4*32)    // 8192
__device__ uint32_t g_w0h[NW0], g_w0l[NW0];
__device__ uint32_t g_w1h[NW1], g_w1l[NW1];

__device__ __forceinline__ void mma_bf16(float* c, const uint32_t* a, const uint32_t* b) {
    asm volatile("mma.sync.aligned.m16n8k16.row.col.f32.bf16.bf16.f32 "
        "{%0,%1,%2,%3}, {%4,%5,%6,%7}, {%8,%9}, {%0,%1,%2,%3};"
        : "+f"(c[0]), "+f"(c[1]), "+f"(c[2]), "+f"(c[3])
        : "r"(a[0]), "r"(a[1]), "r"(a[2]), "r"(a[3]), "r"(b[0]), "r"(b[1]));
}
__device__ __forceinline__ void split2(float v0, float v1, uint32_t& hw, uint32_t& lw) {
    __nv_bfloat16 h0 = __float2bfloat16(v0), h1 = __float2bfloat16(v1);
    __nv_bfloat16 l0 = __float2bfloat16(v0 - __bfloat162float(h0));
    __nv_bfloat16 l1 = __float2bfloat16(v1 - __bfloat162float(h1));
    hw = (uint32_t)__bfloat16_as_ushort(h0) | ((uint32_t)__bfloat16_as_ushort(h1) << 16);
    lw = (uint32_t)__bfloat16_as_ushort(l0) | ((uint32_t)__bfloat16_as_ushort(l1) << 16);
}

// Prep: pack W as A-operand fragments. slot i = ((ks*8+mi)*4+r)*32 + l holds
// {W[m][k], W[m][k+1]}, m = mi*16+(l>>2)+(r&1)*8, k = ks*16+(l&3)*2+(r>>1)*8.
__global__ __launch_bounds__(256) void prep_kernel(const float* __restrict__ W0,
                                                   const float* __restrict__ W1) {
    int i = blockIdx.x * 256 + threadIdx.x;
    if (i < NW0) {
        int l = i & 31, r = (i >> 5) & 3, mi = (i >> 7) & 7, ks = i >> 10;
        int m = mi*16 + (l >> 2) + (r & 1)*8;
        int k = ks*16 + (l & 3)*2 + (r >> 1)*8;
        split2(W0[m*192 + k], W0[m*192 + k + 1], g_w0h[i], g_w0l[i]);
    } else if (i < NW0 + NW1) {
        int j = i - NW0;
        int l = j & 31, r = (j >> 5) & 3, mi = (j >> 7) & 7, ks = j >> 10;
        int m = mi*16 + (l >> 2) + (r & 1)*8;
        int k = ks*16 + (l & 3)*2 + (r >> 1)*8;
        split2(W1[m*128 + k], W1[m*128 + k + 1], g_w1h[j], g_w1l[j]);
    }
}

// smem (bytes): XH[0,19200) XL[19200,38400) — dead after A'
//   yT h/l [0,14336),[14336,28672)  (alias XH/XL; y3T later)  sOut [28672,29696)
//   y2 h/l [38400,51456),[51456,64512)   A48 h/l [64512,69888),[69888,75264)
#define OFF_XH    0
#define OFF_XL    19200
#define OFF_YTH   0
#define OFF_YTL   14336
#define OFF_OUT   28672
#define OFF_Y2H   38400
#define OFF_Y2L   51456
#define OFF_A48H  64512
#define OFF_A48L  69888
#define SMEM_BYTES 75264     // 3 blocks/SM

__global__ __launch_bounds__(128, 3) void fused_kernel(
    const float* __restrict__ x,  const float* __restrict__ A,
    const float* __restrict__ b0, const float* __restrict__ b1,
    float* __restrict__ out)
{
    extern __shared__ char sm[];
    uint32_t* XHu  = reinterpret_cast<uint32_t*>(sm + OFF_XH);
    uint32_t* XLu  = reinterpret_cast<uint32_t*>(sm + OFF_XL);
    uint32_t* YTHu = reinterpret_cast<uint32_t*>(sm + OFF_YTH);
    uint32_t* YTLu = reinterpret_cast<uint32_t*>(sm + OFF_YTL);
    uint32_t* Y2Hu = reinterpret_cast<uint32_t*>(sm + OFF_Y2H);
    uint32_t* Y2Lu = reinterpret_cast<uint32_t*>(sm + OFF_Y2L);
    uint32_t* AHu  = reinterpret_cast<uint32_t*>(sm + OFF_A48H);
    uint32_t* ALu  = reinterpret_cast<uint32_t*>(sm + OFF_A48L);
    float*    sOut = reinterpret_cast<float*>(sm + OFF_OUT);

    const int bt0 = blockIdx.x * 2;
    const int t = threadIdx.x;
    const int wid = t >> 5, l = t & 31;
    const int gr = l >> 2, gc = l & 3;
    const int n0 = wid * 32;          // mix N-range (h cols)
    const int miG = wid * 2;          // A'/C' M-range base (2 mi of 16 rows)

    // ---- Stage: x -> bf16 hi/lo rows 0-21,24-45 + zero pad rows; A48 ----
    {
        const float* xr = x + (size_t)bt0 * (22*192);
        for (int i = t; i < 44*24; i += 128) {
            int row = i / 24, cr = i - row * 24;
            int srow = (row < 22) ? row : row + 2;
            const float4* g4 = reinterpret_cast<const float4*>(xr + row*192 + cr*8);
            float4 a = g4[0], b = g4[1];
            uint32_t hw[4], lw[4];
            split2(a.x, a.y, hw[0], lw[0]); split2(a.z, a.w, hw[1], lw[1]);
            split2(b.x, b.y, hw[2], lw[2]); split2(b.z, b.w, hw[3], lw[3]);
            *reinterpret_cast<uint4*>(sm + OFF_XH + srow*400 + cr*16) =
                make_uint4(hw[0], hw[1], hw[2], hw[3]);
            *reinterpret_cast<uint4*>(sm + OFF_XL + srow*400 + cr*16) =
                make_uint4(lw[0], lw[1], lw[2], lw[3]);
        }
        // zero X pad rows 22,23,46,47 (both buffers)
        for (int i = t; i < 800; i += 128) {
            int buf = i / 400, rem = i - buf*400;
            int rsel = rem / 100, w = rem - rsel*100;
            int row = (rsel < 2) ? 22 + rsel : 44 + rsel;   // 22,23,46,47
            (buf ? XLu : XHu)[row*100 + w] = 0;
        }
        // zero A48 (48x28 words each buffer), then scatter entries
        for (int i = t; i < 2688; i += 128) {
            int buf = i / 1344, w = i - buf*1344;
            (buf ? ALu : AHu)[w] = 0;
        }
        __syncthreads();
        const float* Ag = A + (size_t)bt0 * 484;
        for (int i = t; i < 968; i += 128) {
            int btl = i / 484, rem = i - btl*484;
            int c = rem / 22, j = rem - c*22;
            float v = Ag[i];
            __nv_bfloat16 hi = __float2bfloat16(v);
            __nv_bfloat16 lo = __float2bfloat16(v - __bfloat162float(hi));
            int row = btl*24 + c, col = btl*24 + j;
            *reinterpret_cast<__nv_bfloat16*>(sm + OFF_A48H + row*112 + col*2) = hi;
            *reinterpret_cast<__nv_bfloat16*>(sm + OFF_A48L + row*112 + col*2) = lo;
        }
    }
    __syncthreads();

    // ==== Phase A': yT[h,c] = W0 @ x^T  (M=128: 2mi/warp, N=48: 6tt, K=192) ====
    float acc[2][6][4];
    #pragma unroll
    for (int mi = 0; mi < 2; mi++)
        #pragma unroll
        for (int tt = 0; tt < 6; tt++)
            #pragma unroll
            for (int q = 0; q < 4; q++) acc[mi][tt][q] = 0.f;

    for (int ks = 0; ks < 12; ks++) {
        uint32_t awh[2][4], awl[2][4], bxh[6][2], bxl[6][2];
        #pragma unroll
        for (int mi = 0; mi < 2; mi++) {
            const uint32_t* pH = g_w0h + (ks*8 + miG + mi)*128 + l;
            const uint32_t* pL = g_w0l + (ks*8 + miG + mi)*128 + l;
            #pragma unroll
            for (int r = 0; r < 4; r++) { awh[mi][r] = pH[r*32]; awl[mi][r] = pL[r*32]; }
        }
        #pragma unroll
        for (int tt = 0; tt < 6; tt++) {
            int w = (tt*8 + gr)*100 + ks*8 + gc;
            bxh[tt][0] = XHu[w]; bxh[tt][1] = XHu[w + 4];
            bxl[tt][0] = XLu[w]; bxl[tt][1] = XLu[w + 4];
        }
        #pragma unroll
        for (int mi = 0; mi < 2; mi++)
            #pragma unroll
            for (int tt = 0; tt < 6; tt++) mma_bf16(acc[mi][tt], awh[mi], bxh[tt]);
        #pragma unroll
        for (int mi = 0; mi < 2; mi++)
            #pragma unroll
            for (int tt = 0; tt < 6; tt++) mma_bf16(acc[mi][tt], awl[mi], bxh[tt]);
        #pragma unroll
        for (int mi = 0; mi < 2; mi++)
            #pragma unroll
            for (int tt = 0; tt < 6; tt++) mma_bf16(acc[mi][tt], awh[mi], bxl[tt]);
    }
    __syncthreads();     // X reads done; yT may overwrite region

    #pragma unroll
    for (int mi = 0; mi < 2; mi++)
        #pragma unroll
        for (int tt = 0; tt < 6; tt++) {
            int m = (miG + mi)*16 + gr;
            int wd = m*28 + tt*4 + gc;
            uint32_t hw, lw;
            split2(acc[mi][tt][0], acc[mi][tt][1], hw, lw);
            YTHu[wd] = hw; YTLu[wd] = lw;
            split2(acc[mi][tt][2], acc[mi][tt][3], hw, lw);
            YTHu[wd + 224] = hw; YTLu[wd + 224] = lw;   // row m+8
        }
    __syncthreads();

    // ==== Mix1: y2[c,h] = relu(b0 + A48 @ y)  (M=48: 3mi, N=32/warp: 4tt, K=48) ====
    {
        float ac[3][4][4];
        #pragma unroll
        for (int mi = 0; mi < 3; mi++)
            #pragma unroll
            for (int tt = 0; tt < 4; tt++)
                #pragma unroll
                for (int q = 0; q < 4; q++) ac[mi][tt][q] = 0.f;

        #pragma unroll
        for (int ksm = 0; ksm < 3; ksm++) {
            uint32_t aah[3][4], aal[3][4], byh[4][2], byl[4][2];
            #pragma unroll
            for (int mi = 0; mi < 3; mi++) {
                int w = (mi*16 + gr)*28 + ksm*8 + gc;
                aah[mi][0] = AHu[w];       aah[mi][1] = AHu[w + 224];
                aah[mi][2] = AHu[w + 4];   aah[mi][3] = AHu[w + 228];
                aal[mi][0] = ALu[w];       aal[mi][1] = ALu[w + 224];
                aal[mi][2] = ALu[w + 4];   aal[mi][3] = ALu[w + 228];
            }
            #pragma unroll
            for (int tt = 0; tt < 4; tt++) {
                int w = (n0 + tt*8 + gr)*28 + ksm*8 + gc;
                byh[tt][0] = YTHu[w]; byh[tt][1] = YTHu[w + 4];
                byl[tt][0] = YTLu[w]; byl[tt][1] = YTLu[w + 4];
            }
            #pragma unroll
            for (int mi = 0; mi < 3; mi++)
                #pragma unroll
                for (int tt = 0; tt < 4; tt++) mma_bf16(ac[mi][tt], aah[mi], byh[tt]);
            #pragma unroll
            for (int mi = 0; mi < 3; mi++)
                #pragma unroll
                for (int tt = 0; tt < 4; tt++) mma_bf16(ac[mi][tt], aal[mi], byh[tt]);
            #pragma unroll
            for (int mi = 0; mi < 3; mi++)
                #pragma unroll
                for (int tt = 0; tt < 4; tt++) mma_bf16(ac[mi][tt], aah[mi], byl[tt]);
        }
        // epilogue: +b0, relu, split -> y2 (stride 68 words), all 48 rows
        #pragma unroll
        for (int tt = 0; tt < 4; tt++) {
            int c0 = n0 + tt*8 + gc*2;
            float bb0 = __ldg(b0 + c0), bb1 = __ldg(b0 + c0 + 1);
            #pragma unroll
            for (int mi = 0; mi < 3; mi++) {
                int row = mi*16 + gr;
                int wd = row*68 + (c0 >> 1);
                uint32_t hw, lw;
                split2(fmaxf(ac[mi][tt][0] + bb0, 0.f), fmaxf(ac[mi][tt][1] + bb1, 0.f), hw, lw);
                Y2Hu[wd] = hw; Y2Lu[wd] = lw;
                split2(fmaxf(ac[mi][tt][2] + bb0, 0.f), fmaxf(ac[mi][tt][3] + bb1, 0.f), hw, lw);
                Y2Hu[wd + 544] = hw; Y2Lu[wd + 544] = lw;   // row+8
            }
        }
    }
    __syncthreads();

    // ==== Phase C': y3T[h,c] = W1 @ y2^T  (M=128, N=48, K=128: 8 ks) ====
    #pragma unroll
    for (int mi = 0; mi < 2; mi++)
        #pragma unroll
        for (int tt = 0; tt < 6; tt++)
            #pragma unroll
            for (int q = 0; q < 4; q++) acc[mi][tt][q] = 0.f;

    for (int ks = 0; ks < 8; ks++) {
        uint32_t awh[2][4], awl[2][4], bxh[6][2], bxl[6][2];
        #pragma unroll
        for (int mi = 0; mi < 2; mi++) {
            const uint32_t* pH = g_w1h + (ks*8 + miG + mi)*128 + l;
            const uint32_t* pL = g_w1l + (ks*8 + miG + mi)*128 + l;
            #pragma unroll
            for (int r = 0; r < 4; r++) { awh[mi][r] = pH[r*32]; awl[mi][r] = pL[r*32]; }
        }
        #pragma unroll
        for (int tt = 0; tt < 6; tt++) {
            int w = (tt*8 + gr)*68 + ks*8 + gc;
            bxh[tt][0] = Y2Hu[w]; bxh[tt][1] = Y2Hu[w + 4];
            bxl[tt][0] = Y2Lu[w]; bxl[tt][1] = Y2Lu[w + 4];
        }
        #pragma unroll
        for (int mi = 0; mi < 2; mi++)
            #pragma unroll
            for (int tt = 0; tt < 6; tt++) mma_bf16(acc[mi][tt], awh[mi], bxh[tt]);
        #pragma unroll
        for (int mi = 0; mi < 2; mi++)
            #pragma unroll
            for (int tt = 0; tt < 6; tt++) mma_bf16(acc[mi][tt], awl[mi], bxh[tt]);
        #pragma unroll
        for (int mi = 0; mi < 2; mi++)
            #pragma unroll
            for (int tt = 0; tt < 6; tt++) mma_bf16(acc[mi][tt], awh[mi], bxl[tt]);
    }
    // y3T -> yT region (dead since mix1; disjoint from y2 reads) — no barrier
    #pragma unroll
    for (int mi = 0; mi < 2; mi++)
        #pragma unroll
        for (int tt = 0; tt < 6; tt++) {
            int m = (miG + mi)*16 + gr;
            int wd = m*28 + tt*4 + gc;
            uint32_t hw, lw;
            split2(acc[mi][tt][0], acc[mi][tt][1], hw, lw);
            YTHu[wd] = hw; YTLu[wd] = lw;
            split2(acc[mi][tt][2], acc[mi][tt][3], hw, lw);
            YTHu[wd + 224] = hw; YTLu[wd + 224] = lw;
        }
    __syncthreads();

    // ==== Mix2: out = mean_c relu(b1 + A48 @ y3) ====
    {
        float ac[3][4][4];
        #pragma unroll
        for (int mi = 0; mi < 3; mi++)
            #pragma unroll
            for (int tt = 0; tt < 4; tt++)
                #pragma unroll
                for (int q = 0; q < 4; q++) ac[mi][tt][q] = 0.f;

        #pragma unroll
        for (int ksm = 0; ksm < 3; ksm++) {
            uint32_t aah[3][4], aal[3][4], byh[4][2], byl[4][2];
            #pragma unroll
            for (int mi = 0; mi < 3; mi++) {
                int w = (mi*16 + gr)*28 + ksm*8 + gc;
                aah[mi][0] = AHu[w];       aah[mi][1] = AHu[w + 224];
                aah[mi][2] = AHu[w + 4];   aah[mi][3] = AHu[w + 228];
                aal[mi][0] = ALu[w];       aal[mi][1] = ALu[w + 224];
                aal[mi][2] = ALu[w + 4];   aal[mi][3] = ALu[w + 228];
            }
            #pragma unroll
            for (int tt = 0; tt < 4; tt++) {
                int w = (n0 + tt*8 + gr)*28 + ksm*8 + gc;
                byh[tt][0] = YTHu[w]; byh[tt][1] = YTHu[w + 4];
                byl[tt][0] = YTLu[w]; byl[tt][1] = YTLu[w + 4];
            }
            #pragma unroll
            for (int mi = 0; mi < 3; mi++)
                #pragma unroll
                for (int tt = 0; tt < 4; tt++) mma_bf16(ac[mi][tt], aah[mi], byh[tt]);
            #pragma unroll
            for (int mi = 0; mi < 3; mi++)
                #pragma unroll
                for (int tt = 0; tt < 4; tt++) mma_bf16(ac[mi][tt], aal[mi], byh[tt]);
            #pragma unroll
            for (int mi = 0; mi < 3; mi++)
                #pragma unroll
                for (int tt = 0; tt < 4; tt++) mma_bf16(ac[mi][tt], aah[mi], byl[tt]);
        }
        // epilogue: relu(+b1) accumulate per (btl, col) over this thread's rows,
        // shfl-reduce across gr lanes, gr==0 lanes write sOut.
        float p0[4][2], p1[4][2];
        #pragma unroll
        for (int tt = 0; tt < 4; tt++) { p0[tt][0]=0.f; p0[tt][1]=0.f; p1[tt][0]=0.f; p1[tt][1]=0.f; }
        #pragma unroll
        for (int tt = 0; tt < 4; tt++) {
            int c0 = n0 + tt*8 + gc*2;
            float bb0 = __ldg(b1 + c0), bb1 = __ldg(b1 + c0 + 1);
            #pragma unroll
            for (int mi = 0; mi < 3; mi++) {
                int rlo = mi*16 + gr, rhi = rlo + 8;
                float v0 = fmaxf(ac[mi][tt][0] + bb0, 0.f);
                float v1 = fmaxf(ac[mi][tt][1] + bb1, 0.f);
                float v2 = fmaxf(ac[mi][tt][2] + bb0, 0.f);
                float v3 = fmaxf(ac[mi][tt][3] + bb1, 0.f);
                if (rlo < 22)                    { p0[tt][0] += v0; p0[tt][1] += v1; }
                else if (rlo >= 24 && rlo < 46)  { p1[tt][0] += v0; p1[tt][1] += v1; }
                if (rhi < 22)                    { p0[tt][0] += v2; p0[tt][1] += v3; }
                else if (rhi >= 24 && rhi < 46)  { p1[tt][0] += v2; p1[tt][1] += v3; }
            }
        }
        #pragma unroll
        for (int tt = 0; tt < 4; tt++)
            #pragma unroll
            for (int q = 0; q < 2; q++) {
                #pragma unroll
                for (int m_ = 4; m_ <= 16; m_ <<= 1) {
                    p0[tt][q] += __shfl_xor_sync(0xFFFFFFFFu, p0[tt][q], m_);
                    p1[tt][q] += __shfl_xor_sync(0xFFFFFFFFu, p1[tt][q], m_);
                }
            }
        if (gr == 0) {
            #pragma unroll
            for (int tt = 0; tt < 4; tt++) {
                int c0 = n0 + tt*8 + gc*2;
                sOut[c0]       = p0[tt][0];  sOut[c0 + 1]       = p0[tt][1];
                sOut[128 + c0] = p1[tt][0];  sOut[128 + c0 + 1] = p1[tt][1];
            }
        }
    }
    __syncthreads();
    out[(size_t)bt0*128 + t]     = sOut[t]       * (1.f/22.f);
    out[(size_t)(bt0+1)*128 + t] = sOut[128 + t] * (1.f/22.f);
}

extern "C" void kernel_launch(void* const* d_in, const int* in_sizes, int n_in,
                              void* d_out, int out_size) {
    const float* x  = (const float*)d_in[0];   // [32,512,22,192]
    const float* A  = (const float*)d_in[1];   // [16384,22,22]
    const float* W0 = (const float*)d_in[2];   // [128,192]
    const float* b0 = (const float*)d_in[3];
    const float* W1 = (const float*)d_in[4];   // [128,128]
    const float* b1 = (const float*)d_in[5];
    float* out = (float*)d_out;                // [16384,128]

    cudaFuncSetAttribute(fused_kernel, cudaFuncAttributeMaxDynamicSharedMemorySize, SMEM_BYTES);
    prep_kernel<<<(NW0 + NW1 + 255) / 256, 256>>>(W0, W1);
    fused_kernel<<<NBLK, 128, SMEM_BYTES>>>(x, A, b0, b1, out);
}